// round 3
// baseline (speedup 1.0000x reference)
#include <cuda_runtime.h>

// Problem constants
#define NB  8            // batch
#define NPT 1024         // points (Nq == Nk)
#define DD  512          // model dim
#define NH  8            // heads
#define DH  64           // head dim
#define MM  (NB * NPT)   // 8192 flattened rows
#define SCALE 0.04419417382415922f   // 1/sqrt(512)

// ---------------- scratch (device globals; allocation-free) ----------------
__device__ float g_q[(size_t)MM * DD];                 // 16 MB
__device__ float g_k[(size_t)MM * DD];
__device__ float g_v[(size_t)MM * DD];
__device__ float g_o[(size_t)MM * DD];                 // Oh concat, pre out-proj
__device__ float g_A[(size_t)NH * NB * NPT * NPT];     // 256 MB attention matrix

// ======================================================================
// GEMM: C[M,512] = X[M,512] @ W[512,512] (+bias), optional relu+residual
// 64x64 block tile, BK=16, 256 threads, 4x4 micro-tile.
// EPI==0: C = XW + b     EPI==1: C = X + relu(XW + b)
// ======================================================================
template <int EPI>
__global__ void __launch_bounds__(256) gemm512(
    const float* __restrict__ X, const float* __restrict__ W,
    const float* __restrict__ bias, float* __restrict__ C)
{
    __shared__ float Xs[16][64];   // [k][m]
    __shared__ float Ws[16][64];   // [k][n]
    const int tid = threadIdx.x;
    const int tx = tid & 15, ty = tid >> 4;
    const int m0 = blockIdx.y << 6;
    const int n0 = blockIdx.x << 6;

    const int lm = tid >> 2;            // 0..63
    const int lk = (tid & 3) << 2;      // 0,4,8,12
    const int wk = tid >> 4;            // 0..15
    const int wn = (tid & 15) << 2;     // 0..60

    float acc[4][4];
#pragma unroll
    for (int i = 0; i < 4; i++)
#pragma unroll
        for (int j = 0; j < 4; j++) acc[i][j] = 0.f;

    for (int k0 = 0; k0 < DD; k0 += 16) {
        float4 xv = *(const float4*)(X + (size_t)(m0 + lm) * DD + k0 + lk);
        Xs[lk + 0][lm] = xv.x; Xs[lk + 1][lm] = xv.y;
        Xs[lk + 2][lm] = xv.z; Xs[lk + 3][lm] = xv.w;
        *(float4*)&Ws[wk][wn] = *(const float4*)(W + (size_t)(k0 + wk) * DD + n0 + wn);
        __syncthreads();
#pragma unroll
        for (int k = 0; k < 16; k++) {
            float4 a  = *(const float4*)&Xs[k][ty << 2];
            float4 bb = *(const float4*)&Ws[k][tx << 2];
            float av[4] = {a.x, a.y, a.z, a.w};
            float bv[4] = {bb.x, bb.y, bb.z, bb.w};
#pragma unroll
            for (int i = 0; i < 4; i++)
#pragma unroll
                for (int j = 0; j < 4; j++) acc[i][j] += av[i] * bv[j];
        }
        __syncthreads();
    }

    const int n = n0 + (tx << 2);
    float4 bb = *(const float4*)(bias + n);
#pragma unroll
    for (int i = 0; i < 4; i++) {
        const int row = m0 + (ty << 2) + i;
        float4 v;
        v.x = acc[i][0] + bb.x;
        v.y = acc[i][1] + bb.y;
        v.z = acc[i][2] + bb.z;
        v.w = acc[i][3] + bb.w;
        if (EPI == 1) {
            float4 r = *(const float4*)(X + (size_t)row * DD + n);
            v.x = r.x + fmaxf(v.x, 0.f);
            v.y = r.y + fmaxf(v.y, 0.f);
            v.z = r.z + fmaxf(v.z, 0.f);
            v.w = r.w + fmaxf(v.w, 0.f);
        }
        *(float4*)(C + (size_t)row * DD + n) = v;
    }
}

// ======================================================================
// Scores: per (h,b): S[i,j] = scale * sum_d q[b,i,h*64+d] * k[b,j,h*64+d]
// 64x64 tile, full K=64 resident. grid (j_tiles=16, i_tiles=16, hb=64)
// ======================================================================
__global__ void __launch_bounds__(256) scores_kernel()
{
    __shared__ float Qs[64][68];   // [d][i], pad 68 keeps float4 alignment
    __shared__ float Ks[64][68];   // [d][j]
    const int tid = threadIdx.x;
    const int tx = tid & 15, ty = tid >> 4;
    const int hb = blockIdx.z;
    const int h = hb >> 3, b = hb & 7;
    const int i0 = blockIdx.y << 6;
    const int j0 = blockIdx.x << 6;

#pragma unroll
    for (int t = 0; t < 4; t++) {
        int c   = tid + (t << 8);       // 0..1023
        int row = c >> 4;               // 0..63
        int d4  = (c & 15) << 2;        // 0..60
        float4 qv = *(const float4*)(g_q + (size_t)(b * NPT + i0 + row) * DD + h * DH + d4);
        Qs[d4 + 0][row] = qv.x; Qs[d4 + 1][row] = qv.y;
        Qs[d4 + 2][row] = qv.z; Qs[d4 + 3][row] = qv.w;
        float4 kv = *(const float4*)(g_k + (size_t)(b * NPT + j0 + row) * DD + h * DH + d4);
        Ks[d4 + 0][row] = kv.x; Ks[d4 + 1][row] = kv.y;
        Ks[d4 + 2][row] = kv.z; Ks[d4 + 3][row] = kv.w;
    }
    __syncthreads();

    float acc[4][4];
#pragma unroll
    for (int i = 0; i < 4; i++)
#pragma unroll
        for (int j = 0; j < 4; j++) acc[i][j] = 0.f;

#pragma unroll 8
    for (int d = 0; d < 64; d++) {
        float4 a  = *(const float4*)&Qs[d][ty << 2];
        float4 kk = *(const float4*)&Ks[d][tx << 2];
        float av[4] = {a.x, a.y, a.z, a.w};
        float bv[4] = {kk.x, kk.y, kk.z, kk.w};
#pragma unroll
        for (int i = 0; i < 4; i++)
#pragma unroll
            for (int j = 0; j < 4; j++) acc[i][j] += av[i] * bv[j];
    }

    float* out = g_A + (size_t)hb * NPT * NPT;
#pragma unroll
    for (int i = 0; i < 4; i++) {
        float4 v;
        v.x = acc[i][0] * SCALE; v.y = acc[i][1] * SCALE;
        v.z = acc[i][2] * SCALE; v.w = acc[i][3] * SCALE;
        *(float4*)(out + (size_t)(i0 + (ty << 2) + i) * NPT + j0 + (tx << 2)) = v;
    }
}

// ======================================================================
// Row softmax, in place on g_A. One block per row of 1024.
// ======================================================================
__global__ void __launch_bounds__(256) softmax_kernel()
{
    const int tid = threadIdx.x;
    float* p = g_A + (size_t)blockIdx.x * NPT;
    float4 v = ((float4*)p)[tid];

    float m = fmaxf(fmaxf(v.x, v.y), fmaxf(v.z, v.w));
#pragma unroll
    for (int o = 16; o > 0; o >>= 1)
        m = fmaxf(m, __shfl_xor_sync(0xffffffffu, m, o));

    __shared__ float sh[8];
    __shared__ float bval;
    if ((tid & 31) == 0) sh[tid >> 5] = m;
    __syncthreads();
    if (tid == 0) {
        float mm = sh[0];
#pragma unroll
        for (int i = 1; i < 8; i++) mm = fmaxf(mm, sh[i]);
        bval = mm;
    }
    __syncthreads();
    m = bval;

    v.x = __expf(v.x - m); v.y = __expf(v.y - m);
    v.z = __expf(v.z - m); v.w = __expf(v.w - m);
    float s = v.x + v.y + v.z + v.w;
#pragma unroll
    for (int o = 16; o > 0; o >>= 1)
        s += __shfl_xor_sync(0xffffffffu, s, o);
    __syncthreads();
    if ((tid & 31) == 0) sh[tid >> 5] = s;
    __syncthreads();
    if (tid == 0) {
        float ss = 0.f;
#pragma unroll
        for (int i = 0; i < 8; i++) ss += sh[i];
        bval = ss;
    }
    __syncthreads();
    float inv = 1.0f / bval;
    v.x *= inv; v.y *= inv; v.z *= inv; v.w *= inv;
    ((float4*)p)[tid] = v;
}

// ======================================================================
// O[b,i,h*64+d] = q[b,i,h*64+d] + sum_j A[hb,i,j] * v[b,j,h*64+d]
// per (hb, i-tile): 64 rows x 64 cols, K=1024 in BK=32 chunks.
// grid (i_tiles=16, hb=64)
// ======================================================================
__global__ void __launch_bounds__(256) av_kernel()
{
    __shared__ float As[32][64];   // [kk][i]
    __shared__ float Vs[32][64];   // [kk][d]
    const int tid = threadIdx.x;
    const int tx = tid & 15, ty = tid >> 4;
    const int hb = blockIdx.y;
    const int h = hb >> 3, b = hb & 7;
    const int i0 = blockIdx.x << 6;
    const float* Abase = g_A + (size_t)hb * NPT * NPT;

    float acc[4][4];
#pragma unroll
    for (int i = 0; i < 4; i++)
#pragma unroll
        for (int j = 0; j < 4; j++) acc[i][j] = 0.f;

    for (int k0 = 0; k0 < NPT; k0 += 32) {
#pragma unroll
        for (int t = 0; t < 2; t++) {
            int c  = tid + (t << 8);
            int i  = c >> 3;               // 0..63
            int k4 = (c & 7) << 2;         // 0..28
            float4 av = *(const float4*)(Abase + (size_t)(i0 + i) * NPT + k0 + k4);
            As[k4 + 0][i] = av.x; As[k4 + 1][i] = av.y;
            As[k4 + 2][i] = av.z; As[k4 + 3][i] = av.w;
        }
#pragma unroll
        for (int t = 0; t < 2; t++) {
            int c  = tid + (t << 8);
            int kk = c >> 4;               // 0..31
            int d4 = (c & 15) << 2;        // 0..60
            *(float4*)&Vs[kk][d4] =
                *(const float4*)(g_v + (size_t)(b * NPT + k0 + kk) * DD + h * DH + d4);
        }
        __syncthreads();
#pragma unroll
        for (int kk = 0; kk < 32; kk++) {
            float4 a  = *(const float4*)&As[kk][ty << 2];
            float4 vv = *(const float4*)&Vs[kk][tx << 2];
            float av[4] = {a.x, a.y, a.z, a.w};
            float bv[4] = {vv.x, vv.y, vv.z, vv.w};
#pragma unroll
            for (int i = 0; i < 4; i++)
#pragma unroll
                for (int j = 0; j < 4; j++) acc[i][j] += av[i] * bv[j];
        }
        __syncthreads();
    }

#pragma unroll
    for (int i = 0; i < 4; i++) {
        size_t g = (size_t)(b * NPT + i0 + (ty << 2) + i) * DD + h * DH + (tx << 2);
        float4 r = *(const float4*)(g_q + g);   // residual = projected q
        float4 v;
        v.x = r.x + acc[i][0]; v.y = r.y + acc[i][1];
        v.z = r.z + acc[i][2]; v.w = r.w + acc[i][3];
        *(float4*)(g_o + g) = v;
    }
}

// ======================================================================
// Am[b, j, i] = (1/8) * sum_h A[h, b, i, j]   (transpose via smem tile)
// grid (i_tiles=32, j_tiles=32, b=8), 256 threads (32x8)
// ======================================================================
__global__ void __launch_bounds__(256) meanA_kernel(float* __restrict__ out)
{
    __shared__ float s[32][33];
    const int b  = blockIdx.z;
    const int i0 = blockIdx.x << 5;
    const int j0 = blockIdx.y << 5;
    const int tx = threadIdx.x & 31;
    const int ty = threadIdx.x >> 5;   // 0..7

    float acc[4] = {0.f, 0.f, 0.f, 0.f};
#pragma unroll
    for (int h = 0; h < 8; h++) {
        const float* base = g_A + ((size_t)(h * NB + b) * NPT + i0) * NPT + j0;
#pragma unroll
        for (int r = 0; r < 4; r++)
            acc[r] += base[(size_t)(ty + (r << 3)) * NPT + tx];
    }
#pragma unroll
    for (int r = 0; r < 4; r++) s[ty + (r << 3)][tx] = acc[r] * 0.125f;
    __syncthreads();

    float* ob = out + ((size_t)b * NPT + j0) * NPT + i0;
#pragma unroll
    for (int r = 0; r < 4; r++)
        ob[(size_t)(ty + (r << 3)) * NPT + tx] = s[tx][ty + (r << 3)];
}

// ======================================================================
// Launch
// ======================================================================
extern "C" void kernel_launch(void* const* d_in, const int* in_sizes, int n_in,
                              void* d_out, int out_size)
{
    const float* Q  = (const float*)d_in[0];
    const float* K  = (const float*)d_in[1];
    const float* Wq = (const float*)d_in[2];
    const float* bq = (const float*)d_in[3];
    const float* Wk = (const float*)d_in[4];
    const float* bk = (const float*)d_in[5];
    const float* Wv = (const float*)d_in[6];
    const float* bv = (const float*)d_in[7];
    const float* Wo = (const float*)d_in[8];
    const float* bo = (const float*)d_in[9];
    float* out = (float*)d_out;

    static float *pq = nullptr, *pk = nullptr, *pv = nullptr, *po = nullptr;
    if (!pq) {
        void* t;
        cudaGetSymbolAddress(&t, g_q); pq = (float*)t;
        cudaGetSymbolAddress(&t, g_k); pk = (float*)t;
        cudaGetSymbolAddress(&t, g_v); pv = (float*)t;
        cudaGetSymbolAddress(&t, g_o); po = (float*)t;
    }

    dim3 ggemm(DD / 64, MM / 64);                 // (8, 128)

    gemm512<0><<<ggemm, 256>>>(Q, Wq, bq, pq);
    gemm512<0><<<ggemm, 256>>>(K, Wk, bk, pk);
    gemm512<0><<<ggemm, 256>>>(K, Wv, bv, pv);

    scores_kernel<<<dim3(16, 16, 64), 256>>>();
    softmax_kernel<<<NH * NB * NPT, 256>>>();     // 65536 rows
    av_kernel<<<dim3(16, 64), 256>>>();

    gemm512<1><<<ggemm, 256>>>(po, Wo, bo, out);  // O + relu(O@Wo + bo)
    meanA_kernel<<<dim3(32, 32, 8), 256>>>(out + (size_t)MM * DD);
}

// round 4
// speedup vs baseline: 1.9041x; 1.9041x over previous
#include <cuda_runtime.h>
#include <cstdint>

#define NB  8
#define NPT 1024
#define DD  512
#define NH  8
#define DH  64
#define MM  (NB * NPT)
#define SCALE 0.04419417382415922f   // 1/sqrt(512)

// ---------------- scratch (device globals; allocation-free) ----------------
__device__ float g_q[(size_t)MM * DD];
__device__ float g_k[(size_t)MM * DD];
__device__ float g_v[(size_t)MM * DD];
__device__ float g_o[(size_t)MM * DD];
__device__ float g_A[(size_t)NH * NB * NPT * NPT];   // 256 MB

// ---------------- tf32 mma helpers ----------------
__device__ __forceinline__ uint32_t f2tf(float f) {
    uint32_t u;
    asm("cvt.rna.tf32.f32 %0, %1;" : "=r"(u) : "f"(f));
    return u;
}
__device__ __forceinline__ void mma8(float* c, const uint32_t* a, const uint32_t* b) {
    asm volatile(
        "mma.sync.aligned.m16n8k8.row.col.f32.tf32.tf32.f32 "
        "{%0,%1,%2,%3},{%4,%5,%6,%7},{%8,%9},{%0,%1,%2,%3};"
        : "+f"(c[0]), "+f"(c[1]), "+f"(c[2]), "+f"(c[3])
        : "r"(a[0]), "r"(a[1]), "r"(a[2]), "r"(a[3]), "r"(b[0]), "r"(b[1]));
}

// ======================================================================
// GEMM: C[M,512] = X[M,512] @ W[512,512] + b, optional relu+residual.
// Block 128x64, K-chunk 32, 8 warps (M4 x N2), warp tile 32x32.
// EPI==0: C = XW + b     EPI==1: C = X + relu(XW + b)
// ======================================================================
template <int EPI>
__global__ void __launch_bounds__(256) gemm512_tc(
    const float* __restrict__ X, const float* __restrict__ W,
    const float* __restrict__ bias, float* __restrict__ C)
{
    __shared__ uint32_t Xs[128 * 36];   // stride 36 == 4 (mod 32): A-frag conflict-free
    __shared__ uint32_t Ws[32 * 72];    // stride 72 == 8 (mod 32): B-frag conflict-free
    const int tid = threadIdx.x, lane = tid & 31, w = tid >> 5;
    const int m0 = blockIdx.y << 7, n0 = blockIdx.x << 6;
    const int wm = (w & 3) << 5, wn = (w >> 2) << 5;

    float acc[2][4][4];
#pragma unroll
    for (int mf = 0; mf < 2; mf++)
#pragma unroll
        for (int nf = 0; nf < 4; nf++)
#pragma unroll
            for (int x = 0; x < 4; x++) acc[mf][nf][x] = 0.f;

    const int xr = tid >> 1, xcb = (tid & 1) << 4;
    const int wk = tid >> 3, wnn = (tid & 7) << 3;
    const float* xsrc = X + (size_t)(m0 + xr) * DD + xcb;
    const float* wsrc = W + (size_t)wk * DD + n0 + wnn;
    uint32_t* xdst = &Xs[xr * 36 + xcb];
    uint32_t* wdst = &Ws[wk * 72 + wnn];

    for (int k0 = 0; k0 < DD; k0 += 32) {
        if (k0) __syncthreads();
#pragma unroll
        for (int t = 0; t < 4; t++) {
            float4 v = *(const float4*)(xsrc + k0 + 4 * t);
            xdst[4 * t + 0] = f2tf(v.x); xdst[4 * t + 1] = f2tf(v.y);
            xdst[4 * t + 2] = f2tf(v.z); xdst[4 * t + 3] = f2tf(v.w);
        }
#pragma unroll
        for (int t = 0; t < 2; t++) {
            float4 v = *(const float4*)(wsrc + (size_t)k0 * DD + 4 * t);
            wdst[4 * t + 0] = f2tf(v.x); wdst[4 * t + 1] = f2tf(v.y);
            wdst[4 * t + 2] = f2tf(v.z); wdst[4 * t + 3] = f2tf(v.w);
        }
        __syncthreads();
#pragma unroll
        for (int kk = 0; kk < 32; kk += 8) {
            uint32_t af[2][4], bf[4][2];
#pragma unroll
            for (int mf = 0; mf < 2; mf++) {
                int row = wm + (mf << 4) + (lane >> 2);
                int c = kk + (lane & 3);
                af[mf][0] = Xs[row * 36 + c];
                af[mf][1] = Xs[(row + 8) * 36 + c];
                af[mf][2] = Xs[row * 36 + c + 4];
                af[mf][3] = Xs[(row + 8) * 36 + c + 4];
            }
#pragma unroll
            for (int nf = 0; nf < 4; nf++) {
                int cr = wn + (nf << 3) + (lane >> 2);
                int c = kk + (lane & 3);
                bf[nf][0] = Ws[c * 72 + cr];
                bf[nf][1] = Ws[(c + 4) * 72 + cr];
            }
#pragma unroll
            for (int mf = 0; mf < 2; mf++)
#pragma unroll
                for (int nf = 0; nf < 4; nf++)
                    mma8(acc[mf][nf], af[mf], bf[nf]);
        }
    }

#pragma unroll
    for (int mf = 0; mf < 2; mf++) {
        int row = m0 + wm + (mf << 4) + (lane >> 2);
#pragma unroll
        for (int nf = 0; nf < 4; nf++) {
            int col = n0 + wn + (nf << 3) + ((lane & 3) << 1);
            float2 bb = *(const float2*)(bias + col);
            float2 v0 = make_float2(acc[mf][nf][0] + bb.x, acc[mf][nf][1] + bb.y);
            float2 v1 = make_float2(acc[mf][nf][2] + bb.x, acc[mf][nf][3] + bb.y);
            if (EPI == 1) {
                float2 r0 = *(const float2*)(X + (size_t)row * DD + col);
                float2 r1 = *(const float2*)(X + (size_t)(row + 8) * DD + col);
                v0.x = r0.x + fmaxf(v0.x, 0.f); v0.y = r0.y + fmaxf(v0.y, 0.f);
                v1.x = r1.x + fmaxf(v1.x, 0.f); v1.y = r1.y + fmaxf(v1.y, 0.f);
            }
            *(float2*)(C + (size_t)row * DD + col) = v0;
            *(float2*)(C + (size_t)(row + 8) * DD + col) = v1;
        }
    }
}

// ======================================================================
// Scores: per (h,b): S[i,j] = scale * q[b,i,h*64+:] . k[b,j,h*64+:]
// Block 128x128, K=64 in 2 chunks of 32. 8 warps (M2 x N4), warp 64x32.
// grid (8, 8, 64)
// ======================================================================
__global__ void __launch_bounds__(256) scores_tc()
{
    __shared__ uint32_t Qs[128 * 36];
    __shared__ uint32_t Ks[128 * 36];
    const int tid = threadIdx.x, lane = tid & 31, w = tid >> 5;
    const int hb = blockIdx.z, h = hb >> 3, b = hb & 7;
    const int i0 = blockIdx.y << 7, j0 = blockIdx.x << 7;
    const int wm = (w & 1) << 6, wn = (w >> 1) << 5;

    float acc[4][4][4];
#pragma unroll
    for (int mf = 0; mf < 4; mf++)
#pragma unroll
        for (int nf = 0; nf < 4; nf++)
#pragma unroll
            for (int x = 0; x < 4; x++) acc[mf][nf][x] = 0.f;

    const int r = tid >> 1, cb = (tid & 1) << 4;
    const float* qsrc = g_q + (size_t)(b * NPT + i0 + r) * DD + h * DH + cb;
    const float* ksrc = g_k + (size_t)(b * NPT + j0 + r) * DD + h * DH + cb;
    uint32_t* qdst = &Qs[r * 36 + cb];
    uint32_t* kdst = &Ks[r * 36 + cb];

    for (int k0 = 0; k0 < DH; k0 += 32) {
        if (k0) __syncthreads();
#pragma unroll
        for (int t = 0; t < 4; t++) {
            float4 v = *(const float4*)(qsrc + k0 + 4 * t);
            qdst[4 * t + 0] = f2tf(v.x); qdst[4 * t + 1] = f2tf(v.y);
            qdst[4 * t + 2] = f2tf(v.z); qdst[4 * t + 3] = f2tf(v.w);
            float4 u = *(const float4*)(ksrc + k0 + 4 * t);
            kdst[4 * t + 0] = f2tf(u.x); kdst[4 * t + 1] = f2tf(u.y);
            kdst[4 * t + 2] = f2tf(u.z); kdst[4 * t + 3] = f2tf(u.w);
        }
        __syncthreads();
#pragma unroll
        for (int kk = 0; kk < 32; kk += 8) {
            uint32_t af[4][4], bf[4][2];
#pragma unroll
            for (int mf = 0; mf < 4; mf++) {
                int row = wm + (mf << 4) + (lane >> 2);
                int c = kk + (lane & 3);
                af[mf][0] = Qs[row * 36 + c];
                af[mf][1] = Qs[(row + 8) * 36 + c];
                af[mf][2] = Qs[row * 36 + c + 4];
                af[mf][3] = Qs[(row + 8) * 36 + c + 4];
            }
#pragma unroll
            for (int nf = 0; nf < 4; nf++) {
                int cr = wn + (nf << 3) + (lane >> 2);
                int c = kk + (lane & 3);
                bf[nf][0] = Ks[cr * 36 + c];
                bf[nf][1] = Ks[cr * 36 + c + 4];
            }
#pragma unroll
            for (int mf = 0; mf < 4; mf++)
#pragma unroll
                for (int nf = 0; nf < 4; nf++)
                    mma8(acc[mf][nf], af[mf], bf[nf]);
        }
    }

    float* out = g_A + (size_t)hb * NPT * NPT;
#pragma unroll
    for (int mf = 0; mf < 4; mf++) {
        int row = i0 + wm + (mf << 4) + (lane >> 2);
#pragma unroll
        for (int nf = 0; nf < 4; nf++) {
            int col = j0 + wn + (nf << 3) + ((lane & 3) << 1);
            float2 v0 = make_float2(acc[mf][nf][0] * SCALE, acc[mf][nf][1] * SCALE);
            float2 v1 = make_float2(acc[mf][nf][2] * SCALE, acc[mf][nf][3] * SCALE);
            *(float2*)(out + (size_t)row * NPT + col) = v0;
            *(float2*)(out + (size_t)(row + 8) * NPT + col) = v1;
        }
    }
}

// ======================================================================
// Row softmax, in place on g_A.
// ======================================================================
__global__ void __launch_bounds__(256) softmax_kernel()
{
    const int tid = threadIdx.x;
    float* p = g_A + (size_t)blockIdx.x * NPT;
    float4 v = ((float4*)p)[tid];

    float m = fmaxf(fmaxf(v.x, v.y), fmaxf(v.z, v.w));
#pragma unroll
    for (int o = 16; o > 0; o >>= 1)
        m = fmaxf(m, __shfl_xor_sync(0xffffffffu, m, o));

    __shared__ float sh[8];
    __shared__ float bval;
    if ((tid & 31) == 0) sh[tid >> 5] = m;
    __syncthreads();
    if (tid == 0) {
        float mm = sh[0];
#pragma unroll
        for (int i = 1; i < 8; i++) mm = fmaxf(mm, sh[i]);
        bval = mm;
    }
    __syncthreads();
    m = bval;

    v.x = __expf(v.x - m); v.y = __expf(v.y - m);
    v.z = __expf(v.z - m); v.w = __expf(v.w - m);
    float s = v.x + v.y + v.z + v.w;
#pragma unroll
    for (int o = 16; o > 0; o >>= 1)
        s += __shfl_xor_sync(0xffffffffu, s, o);
    __syncthreads();
    if ((tid & 31) == 0) sh[tid >> 5] = s;
    __syncthreads();
    if (tid == 0) {
        float ss = 0.f;
#pragma unroll
        for (int i = 0; i < 8; i++) ss += sh[i];
        bval = ss;
    }
    __syncthreads();
    float inv = 1.0f / bval;
    v.x *= inv; v.y *= inv; v.z *= inv; v.w *= inv;
    ((float4*)p)[tid] = v;
}

// ======================================================================
// AV: O[b,i,h*64+d] = q_proj + sum_j A[hb,i,j] * v[b,j,h*64+d]
// Block 128(i) x 64(d), K-chunk 32, 8 warps (M4 x N2), warp 32x32.
// grid (8, 64)
// ======================================================================
__global__ void __launch_bounds__(256) av_tc()
{
    __shared__ uint32_t As[128 * 36];
    __shared__ uint32_t Vs[32 * 72];
    const int tid = threadIdx.x, lane = tid & 31, w = tid >> 5;
    const int hb = blockIdx.y, h = hb >> 3, b = hb & 7;
    const int i0 = blockIdx.x << 7;
    const int wm = (w & 3) << 5, wn = (w >> 2) << 5;
    const float* Abase = g_A + (size_t)hb * NPT * NPT;

    float acc[2][4][4];
#pragma unroll
    for (int mf = 0; mf < 2; mf++)
#pragma unroll
        for (int nf = 0; nf < 4; nf++)
#pragma unroll
            for (int x = 0; x < 4; x++) acc[mf][nf][x] = 0.f;

    const int ar = tid >> 1, acb = (tid & 1) << 4;
    const int vk = tid >> 3, vn = (tid & 7) << 3;
    const float* asrc = Abase + (size_t)(i0 + ar) * NPT + acb;
    const float* vsrc = g_v + (size_t)(b * NPT + vk) * DD + h * DH + vn;
    uint32_t* adst = &As[ar * 36 + acb];
    uint32_t* vdst = &Vs[vk * 72 + vn];

    for (int k0 = 0; k0 < NPT; k0 += 32) {
        if (k0) __syncthreads();
#pragma unroll
        for (int t = 0; t < 4; t++) {
            float4 v = *(const float4*)(asrc + k0 + 4 * t);
            adst[4 * t + 0] = f2tf(v.x); adst[4 * t + 1] = f2tf(v.y);
            adst[4 * t + 2] = f2tf(v.z); adst[4 * t + 3] = f2tf(v.w);
        }
        {
            const float* vp = vsrc + (size_t)k0 * DD;
            float4 v = *(const float4*)vp;
            vdst[0] = f2tf(v.x); vdst[1] = f2tf(v.y);
            vdst[2] = f2tf(v.z); vdst[3] = f2tf(v.w);
            float4 u = *(const float4*)(vp + 4);
            vdst[4] = f2tf(u.x); vdst[5] = f2tf(u.y);
            vdst[6] = f2tf(u.z); vdst[7] = f2tf(u.w);
        }
        __syncthreads();
#pragma unroll
        for (int kk = 0; kk < 32; kk += 8) {
            uint32_t af[2][4], bf[4][2];
#pragma unroll
            for (int mf = 0; mf < 2; mf++) {
                int row = wm + (mf << 4) + (lane >> 2);
                int c = kk + (lane & 3);
                af[mf][0] = As[row * 36 + c];
                af[mf][1] = As[(row + 8) * 36 + c];
                af[mf][2] = As[row * 36 + c + 4];
                af[mf][3] = As[(row + 8) * 36 + c + 4];
            }
#pragma unroll
            for (int nf = 0; nf < 4; nf++) {
                int cr = wn + (nf << 3) + (lane >> 2);
                int c = kk + (lane & 3);
                bf[nf][0] = Vs[c * 72 + cr];
                bf[nf][1] = Vs[(c + 4) * 72 + cr];
            }
#pragma unroll
            for (int mf = 0; mf < 2; mf++)
#pragma unroll
                for (int nf = 0; nf < 4; nf++)
                    mma8(acc[mf][nf], af[mf], bf[nf]);
        }
    }

#pragma unroll
    for (int mf = 0; mf < 2; mf++) {
        int row = i0 + wm + (mf << 4) + (lane >> 2);
#pragma unroll
        for (int nf = 0; nf < 4; nf++) {
            int col = wn + (nf << 3) + ((lane & 3) << 1);
            size_t g0 = (size_t)(b * NPT + row) * DD + h * DH + col;
            size_t g1 = (size_t)(b * NPT + row + 8) * DD + h * DH + col;
            float2 r0 = *(const float2*)(g_q + g0);
            float2 r1 = *(const float2*)(g_q + g1);
            float2 o0 = make_float2(r0.x + acc[mf][nf][0], r0.y + acc[mf][nf][1]);
            float2 o1 = make_float2(r1.x + acc[mf][nf][2], r1.y + acc[mf][nf][3]);
            *(float2*)(g_o + g0) = o0;
            *(float2*)(g_o + g1) = o1;
        }
    }
}

// ======================================================================
// Am[b, j, i] = (1/8) * sum_h A[h, b, i, j]   (transpose via smem tile)
// ======================================================================
__global__ void __launch_bounds__(256) meanA_kernel(float* __restrict__ out)
{
    __shared__ float s[32][33];
    const int b  = blockIdx.z;
    const int i0 = blockIdx.x << 5;
    const int j0 = blockIdx.y << 5;
    const int tx = threadIdx.x & 31;
    const int ty = threadIdx.x >> 5;

    float acc[4] = {0.f, 0.f, 0.f, 0.f};
#pragma unroll
    for (int h = 0; h < 8; h++) {
        const float* base = g_A + ((size_t)(h * NB + b) * NPT + i0) * NPT + j0;
#pragma unroll
        for (int r = 0; r < 4; r++)
            acc[r] += base[(size_t)(ty + (r << 3)) * NPT + tx];
    }
#pragma unroll
    for (int r = 0; r < 4; r++) s[ty + (r << 3)][tx] = acc[r] * 0.125f;
    __syncthreads();

    float* ob = out + ((size_t)b * NPT + j0) * NPT + i0;
#pragma unroll
    for (int r = 0; r < 4; r++)
        ob[(size_t)(ty + (r << 3)) * NPT + tx] = s[tx][ty + (r << 3)];
}

// ======================================================================
// Launch
// ======================================================================
extern "C" void kernel_launch(void* const* d_in, const int* in_sizes, int n_in,
                              void* d_out, int out_size)
{
    const float* Q  = (const float*)d_in[0];
    const float* K  = (const float*)d_in[1];
    const float* Wq = (const float*)d_in[2];
    const float* bq = (const float*)d_in[3];
    const float* Wk = (const float*)d_in[4];
    const float* bk = (const float*)d_in[5];
    const float* Wv = (const float*)d_in[6];
    const float* bv = (const float*)d_in[7];
    const float* Wo = (const float*)d_in[8];
    const float* bo = (const float*)d_in[9];
    float* out = (float*)d_out;

    static float *pq = nullptr, *pk = nullptr, *pv = nullptr, *po = nullptr;
    if (!pq) {
        void* t;
        cudaGetSymbolAddress(&t, g_q); pq = (float*)t;
        cudaGetSymbolAddress(&t, g_k); pk = (float*)t;
        cudaGetSymbolAddress(&t, g_v); pv = (float*)t;
        cudaGetSymbolAddress(&t, g_o); po = (float*)t;
    }

    dim3 ggemm(DD / 64, MM / 128);                    // (8, 64)

    gemm512_tc<0><<<ggemm, 256>>>(Q, Wq, bq, pq);
    gemm512_tc<0><<<ggemm, 256>>>(K, Wk, bk, pk);
    gemm512_tc<0><<<ggemm, 256>>>(K, Wv, bv, pv);

    scores_tc<<<dim3(8, 8, 64), 256>>>();
    softmax_kernel<<<NH * NB * NPT, 256>>>();
    av_tc<<<dim3(8, 64), 256>>>();

    gemm512_tc<1><<<ggemm, 256>>>(po, Wo, bo, out);   // O + relu(O@Wo + bo)
    meanA_kernel<<<dim3(32, 32, 8), 256>>>(out + (size_t)MM * DD);
}

// round 5
// speedup vs baseline: 2.3762x; 1.2479x over previous
#include <cuda_runtime.h>
#include <cstdint>

#define NB  8
#define NPT 1024
#define DD  512
#define NH  8
#define DH  64
#define MM  (NB * NPT)
#define SCALE 0.04419417382415922f   // 1/sqrt(512)

// ---------------- scratch (device globals; allocation-free) ----------------
__device__ float g_q[(size_t)MM * DD];
__device__ float g_k[(size_t)MM * DD];
__device__ float g_v[(size_t)MM * DD];
__device__ float g_o[(size_t)MM * DD];
__device__ float g_A[(size_t)NH * NB * NPT * NPT];   // stores U = exp(s) (unnormalized)
__device__ float g_Z[(size_t)NH * NB * NPT];         // stores 1/rowsum

// ---------------- tf32 mma helpers ----------------
__device__ __forceinline__ uint32_t f2tf(float f) {
    uint32_t u;
    asm("cvt.rna.tf32.f32 %0, %1;" : "=r"(u) : "f"(f));
    return u;
}
__device__ __forceinline__ void mma8(float* c, const uint32_t* a, const uint32_t* b) {
    asm volatile(
        "mma.sync.aligned.m16n8k8.row.col.f32.tf32.tf32.f32 "
        "{%0,%1,%2,%3},{%4,%5,%6,%7},{%8,%9},{%0,%1,%2,%3};"
        : "+f"(c[0]), "+f"(c[1]), "+f"(c[2]), "+f"(c[3])
        : "r"(a[0]), "r"(a[1]), "r"(a[2]), "r"(a[3]), "r"(b[0]), "r"(b[1]));
}

// ======================================================================
// GEMM: C[M,512] = X[M,512] @ W[512,512] + b, optional relu+residual.
// (unchanged from R3 — proven)
// ======================================================================
template <int EPI>
__global__ void __launch_bounds__(256) gemm512_tc(
    const float* __restrict__ X, const float* __restrict__ W,
    const float* __restrict__ bias, float* __restrict__ C)
{
    __shared__ uint32_t Xs[128 * 36];
    __shared__ uint32_t Ws[32 * 72];
    const int tid = threadIdx.x, lane = tid & 31, w = tid >> 5;
    const int m0 = blockIdx.y << 7, n0 = blockIdx.x << 6;
    const int wm = (w & 3) << 5, wn = (w >> 2) << 5;

    float acc[2][4][4];
#pragma unroll
    for (int mf = 0; mf < 2; mf++)
#pragma unroll
        for (int nf = 0; nf < 4; nf++)
#pragma unroll
            for (int x = 0; x < 4; x++) acc[mf][nf][x] = 0.f;

    const int xr = tid >> 1, xcb = (tid & 1) << 4;
    const int wk = tid >> 3, wnn = (tid & 7) << 3;
    const float* xsrc = X + (size_t)(m0 + xr) * DD + xcb;
    const float* wsrc = W + (size_t)wk * DD + n0 + wnn;
    uint32_t* xdst = &Xs[xr * 36 + xcb];
    uint32_t* wdst = &Ws[wk * 72 + wnn];

    for (int k0 = 0; k0 < DD; k0 += 32) {
        if (k0) __syncthreads();
#pragma unroll
        for (int t = 0; t < 4; t++) {
            float4 v = *(const float4*)(xsrc + k0 + 4 * t);
            xdst[4 * t + 0] = f2tf(v.x); xdst[4 * t + 1] = f2tf(v.y);
            xdst[4 * t + 2] = f2tf(v.z); xdst[4 * t + 3] = f2tf(v.w);
        }
#pragma unroll
        for (int t = 0; t < 2; t++) {
            float4 v = *(const float4*)(wsrc + (size_t)k0 * DD + 4 * t);
            wdst[4 * t + 0] = f2tf(v.x); wdst[4 * t + 1] = f2tf(v.y);
            wdst[4 * t + 2] = f2tf(v.z); wdst[4 * t + 3] = f2tf(v.w);
        }
        __syncthreads();
#pragma unroll
        for (int kk = 0; kk < 32; kk += 8) {
            uint32_t af[2][4], bf[4][2];
#pragma unroll
            for (int mf = 0; mf < 2; mf++) {
                int row = wm + (mf << 4) + (lane >> 2);
                int c = kk + (lane & 3);
                af[mf][0] = Xs[row * 36 + c];
                af[mf][1] = Xs[(row + 8) * 36 + c];
                af[mf][2] = Xs[row * 36 + c + 4];
                af[mf][3] = Xs[(row + 8) * 36 + c + 4];
            }
#pragma unroll
            for (int nf = 0; nf < 4; nf++) {
                int cr = wn + (nf << 3) + (lane >> 2);
                int c = kk + (lane & 3);
                bf[nf][0] = Ws[c * 72 + cr];
                bf[nf][1] = Ws[(c + 4) * 72 + cr];
            }
#pragma unroll
            for (int mf = 0; mf < 2; mf++)
#pragma unroll
                for (int nf = 0; nf < 4; nf++)
                    mma8(acc[mf][nf], af[mf], bf[nf]);
        }
    }

#pragma unroll
    for (int mf = 0; mf < 2; mf++) {
        int row = m0 + wm + (mf << 4) + (lane >> 2);
#pragma unroll
        for (int nf = 0; nf < 4; nf++) {
            int col = n0 + wn + (nf << 3) + ((lane & 3) << 1);
            float2 bb = *(const float2*)(bias + col);
            float2 v0 = make_float2(acc[mf][nf][0] + bb.x, acc[mf][nf][1] + bb.y);
            float2 v1 = make_float2(acc[mf][nf][2] + bb.x, acc[mf][nf][3] + bb.y);
            if (EPI == 1) {
                float2 r0 = *(const float2*)(X + (size_t)row * DD + col);
                float2 r1 = *(const float2*)(X + (size_t)(row + 8) * DD + col);
                v0.x = r0.x + fmaxf(v0.x, 0.f); v0.y = r0.y + fmaxf(v0.y, 0.f);
                v1.x = r1.x + fmaxf(v1.x, 0.f); v1.y = r1.y + fmaxf(v1.y, 0.f);
            }
            *(float2*)(C + (size_t)row * DD + col) = v0;
            *(float2*)(C + (size_t)(row + 8) * DD + col) = v1;
        }
    }
}

// ======================================================================
// Fused attention: per (hb, i-tile of 128):
//   loop j-chunks of 128:  S = Q.K^T ; U = exp(S*scale) -> g_A + smem(tf32)
//                          Z += rowsum(U) ; O += U.V
//   epilogue: O = q + O / Z ; g_Z = 1/Z
// 512 threads = 16 warps (wM 4 x wN 4). No max-subtraction (|s| << 88).
// Dynamic smem (words): Qs 128x68 | Ks 128x68 | Vs 128x72 | Ps 128x132 | zbuf 512 | invZ 128
// ======================================================================
#define QS_OFF 0
#define KS_OFF (128 * 68)
#define VS_OFF (KS_OFF + 128 * 68)
#define PS_OFF (VS_OFF + 128 * 72)
#define ZB_OFF (PS_OFF + 128 * 132)
#define IZ_OFF (ZB_OFF + 512)
#define FUSED_SMEM_WORDS (IZ_OFF + 128)
#define FUSED_SMEM_BYTES (FUSED_SMEM_WORDS * 4)

extern __shared__ uint32_t smw[];

__global__ void __launch_bounds__(512, 1) fused_attn()
{
    uint32_t* Qs = smw + QS_OFF;
    uint32_t* Ks = smw + KS_OFF;
    uint32_t* Vs = smw + VS_OFF;
    uint32_t* Ps = smw + PS_OFF;
    float* zbuf  = (float*)(smw + ZB_OFF);
    float* invZs = (float*)(smw + IZ_OFF);

    const int tid = threadIdx.x, lane = tid & 31, w = tid >> 5;
    const int wM = w & 3, wN = w >> 2;
    const int hb = blockIdx.y, h = hb >> 3, b = hb & 7;
    const int i0 = blockIdx.x << 7;

    // Load Q tile (128 x 64) once, tf32
    {
        const float* src = g_q + (size_t)(b * NPT + i0) * DD + h * DH;
#pragma unroll
        for (int t = 0; t < 4; t++) {
            int c = tid + (t << 9);          // 0..2047
            int r = c >> 4, k4 = (c & 15) << 2;
            float4 v = *(const float4*)(src + (size_t)r * DD + k4);
            uint32_t* d = Qs + r * 68 + k4;
            d[0] = f2tf(v.x); d[1] = f2tf(v.y); d[2] = f2tf(v.z); d[3] = f2tf(v.w);
        }
    }

    float oacc[2][2][4];
#pragma unroll
    for (int mf = 0; mf < 2; mf++)
#pragma unroll
        for (int nf = 0; nf < 2; nf++)
#pragma unroll
            for (int x = 0; x < 4; x++) oacc[mf][nf][x] = 0.f;
    float zl[4] = {0.f, 0.f, 0.f, 0.f};

    float* Aout = g_A + (size_t)hb * NPT * NPT;

    for (int j0 = 0; j0 < NPT; j0 += 128) {
        __syncthreads();   // prev-chunk PV done before Ks/Vs overwritten

        // Load K,V chunk (128 x 64 each), tf32
        {
            const float* ks = g_k + (size_t)(b * NPT + j0) * DD + h * DH;
            const float* vs = g_v + (size_t)(b * NPT + j0) * DD + h * DH;
#pragma unroll
            for (int t = 0; t < 4; t++) {
                int c = tid + (t << 9);
                int r = c >> 4, k4 = (c & 15) << 2;
                float4 kv = *(const float4*)(ks + (size_t)r * DD + k4);
                uint32_t* d = Ks + r * 68 + k4;
                d[0] = f2tf(kv.x); d[1] = f2tf(kv.y); d[2] = f2tf(kv.z); d[3] = f2tf(kv.w);
                float4 vv = *(const float4*)(vs + (size_t)r * DD + k4);
                uint32_t* e = Vs + r * 72 + k4;
                e[0] = f2tf(vv.x); e[1] = f2tf(vv.y); e[2] = f2tf(vv.z); e[3] = f2tf(vv.w);
            }
        }
        __syncthreads();

        // ---- S = Q.K^T : warp tile 32x32 at (wM*32, wN*32), K=64 ----
        float sacc[2][4][4];
#pragma unroll
        for (int mf = 0; mf < 2; mf++)
#pragma unroll
            for (int nf = 0; nf < 4; nf++)
#pragma unroll
                for (int x = 0; x < 4; x++) sacc[mf][nf][x] = 0.f;

#pragma unroll
        for (int kk = 0; kk < 64; kk += 8) {
            uint32_t af[2][4], bf[4][2];
            const int c = kk + (lane & 3);
#pragma unroll
            for (int mf = 0; mf < 2; mf++) {
                int row = (wM << 5) + (mf << 4) + (lane >> 2);
                af[mf][0] = Qs[row * 68 + c];
                af[mf][1] = Qs[(row + 8) * 68 + c];
                af[mf][2] = Qs[row * 68 + c + 4];
                af[mf][3] = Qs[(row + 8) * 68 + c + 4];
            }
#pragma unroll
            for (int nf = 0; nf < 4; nf++) {
                int cr = (wN << 5) + (nf << 3) + (lane >> 2);
                bf[nf][0] = Ks[cr * 68 + c];
                bf[nf][1] = Ks[cr * 68 + c + 4];
            }
#pragma unroll
            for (int mf = 0; mf < 2; mf++)
#pragma unroll
                for (int nf = 0; nf < 4; nf++)
                    mma8(sacc[mf][nf], af[mf], bf[nf]);
        }

        // ---- exp (no max-subtract), store U to g_A + tf32 P to smem, acc Z ----
#pragma unroll
        for (int mf = 0; mf < 2; mf++) {
            int row = (wM << 5) + (mf << 4) + (lane >> 2);
#pragma unroll
            for (int nf = 0; nf < 4; nf++) {
                int col = (wN << 5) + (nf << 3) + ((lane & 3) << 1);
                float p0 = __expf(sacc[mf][nf][0] * SCALE);
                float p1 = __expf(sacc[mf][nf][1] * SCALE);
                float p2 = __expf(sacc[mf][nf][2] * SCALE);
                float p3 = __expf(sacc[mf][nf][3] * SCALE);
                zl[mf * 2 + 0] += p0 + p1;
                zl[mf * 2 + 1] += p2 + p3;
                Ps[row * 132 + col]       = f2tf(p0);
                Ps[row * 132 + col + 1]   = f2tf(p1);
                Ps[(row + 8) * 132 + col]     = f2tf(p2);
                Ps[(row + 8) * 132 + col + 1] = f2tf(p3);
                *(float2*)(Aout + (size_t)(i0 + row) * NPT + j0 + col)     = make_float2(p0, p1);
                *(float2*)(Aout + (size_t)(i0 + row + 8) * NPT + j0 + col) = make_float2(p2, p3);
            }
        }
        __syncthreads();

        // ---- O += P.V : warp tile 32x16 at (wM*32, wN*16), K=128 ----
#pragma unroll
        for (int kk = 0; kk < 128; kk += 8) {
            uint32_t af[2][4], bf2[2][2];
            const int c = kk + (lane & 3);
#pragma unroll
            for (int mf = 0; mf < 2; mf++) {
                int row = (wM << 5) + (mf << 4) + (lane >> 2);
                af[mf][0] = Ps[row * 132 + c];
                af[mf][1] = Ps[(row + 8) * 132 + c];
                af[mf][2] = Ps[row * 132 + c + 4];
                af[mf][3] = Ps[(row + 8) * 132 + c + 4];
            }
#pragma unroll
            for (int nf = 0; nf < 2; nf++) {
                int cr = (wN << 4) + (nf << 3) + (lane >> 2);
                bf2[nf][0] = Vs[c * 72 + cr];
                bf2[nf][1] = Vs[(c + 4) * 72 + cr];
            }
#pragma unroll
            for (int mf = 0; mf < 2; mf++)
#pragma unroll
                for (int nf = 0; nf < 2; nf++)
                    mma8(oacc[mf][nf], af[mf], bf2[nf]);
        }
    }

    // ---- Z reduce: quad shuffle -> per-wN partials -> rows ----
#pragma unroll
    for (int zi = 0; zi < 4; zi++) {
        zl[zi] += __shfl_xor_sync(0xffffffffu, zl[zi], 1);
        zl[zi] += __shfl_xor_sync(0xffffffffu, zl[zi], 2);
    }
    if ((lane & 3) == 0) {
#pragma unroll
        for (int zi = 0; zi < 4; zi++) {
            int r = (wM << 5) + ((zi >> 1) << 4) + ((zi & 1) << 3) + (lane >> 2);
            zbuf[wN * 128 + r] = zl[zi];
        }
    }
    __syncthreads();
    if (tid < 128) {
        float Z = zbuf[tid] + zbuf[128 + tid] + zbuf[256 + tid] + zbuf[384 + tid];
        float iz = 1.0f / Z;
        invZs[tid] = iz;
        g_Z[(size_t)hb * NPT + i0 + tid] = iz;
    }
    __syncthreads();

    // ---- epilogue: O = q + O/Z (exact fp32 residual) ----
#pragma unroll
    for (int mf = 0; mf < 2; mf++) {
        int row = (wM << 5) + (mf << 4) + (lane >> 2);
        float iz0 = invZs[row], iz1 = invZs[row + 8];
#pragma unroll
        for (int nf = 0; nf < 2; nf++) {
            int cd = (wN << 4) + (nf << 3) + ((lane & 3) << 1);
            size_t gi0 = (size_t)(b * NPT + i0 + row) * DD + h * DH + cd;
            size_t gi1 = gi0 + (size_t)8 * DD;
            float2 q0 = *(const float2*)(g_q + gi0);
            float2 q1 = *(const float2*)(g_q + gi1);
            float2 o0 = make_float2(q0.x + oacc[mf][nf][0] * iz0,
                                    q0.y + oacc[mf][nf][1] * iz0);
            float2 o1 = make_float2(q1.x + oacc[mf][nf][2] * iz1,
                                    q1.y + oacc[mf][nf][3] * iz1);
            *(float2*)(g_o + gi0) = o0;
            *(float2*)(g_o + gi1) = o1;
        }
    }
}

// ======================================================================
// Am[b, j, i] = (1/8) * sum_h U[h,b,i,j] * invZ[h,b,i]   (transpose)
// ======================================================================
__global__ void __launch_bounds__(256) meanA_kernel(float* __restrict__ out)
{
    __shared__ float s[32][33];
    __shared__ float ziv[8][32];
    const int b  = blockIdx.z;
    const int i0 = blockIdx.x << 5;
    const int j0 = blockIdx.y << 5;
    const int tx = threadIdx.x & 31;
    const int ty = threadIdx.x >> 5;

    ziv[ty][tx] = g_Z[(size_t)(ty * NB + b) * NPT + i0 + tx];
    __syncthreads();

    float acc[4] = {0.f, 0.f, 0.f, 0.f};
#pragma unroll
    for (int h = 0; h < 8; h++) {
        const float* base = g_A + ((size_t)(h * NB + b) * NPT + i0) * NPT + j0;
#pragma unroll
        for (int r = 0; r < 4; r++)
            acc[r] += base[(size_t)(ty + (r << 3)) * NPT + tx] * ziv[h][ty + (r << 3)];
    }
#pragma unroll
    for (int r = 0; r < 4; r++) s[ty + (r << 3)][tx] = acc[r] * 0.125f;
    __syncthreads();

    float* ob = out + ((size_t)b * NPT + j0) * NPT + i0;
#pragma unroll
    for (int r = 0; r < 4; r++)
        ob[(size_t)(ty + (r << 3)) * NPT + tx] = s[tx][ty + (r << 3)];
}

// ======================================================================
// Launch
// ======================================================================
extern "C" void kernel_launch(void* const* d_in, const int* in_sizes, int n_in,
                              void* d_out, int out_size)
{
    const float* Q  = (const float*)d_in[0];
    const float* K  = (const float*)d_in[1];
    const float* Wq = (const float*)d_in[2];
    const float* bq = (const float*)d_in[3];
    const float* Wk = (const float*)d_in[4];
    const float* bk = (const float*)d_in[5];
    const float* Wv = (const float*)d_in[6];
    const float* bv = (const float*)d_in[7];
    const float* Wo = (const float*)d_in[8];
    const float* bo = (const float*)d_in[9];
    float* out = (float*)d_out;

    static float *pq = nullptr, *pk = nullptr, *pv = nullptr, *po = nullptr;
    if (!pq) {
        void* t;
        cudaGetSymbolAddress(&t, g_q); pq = (float*)t;
        cudaGetSymbolAddress(&t, g_k); pk = (float*)t;
        cudaGetSymbolAddress(&t, g_v); pv = (float*)t;
        cudaGetSymbolAddress(&t, g_o); po = (float*)t;
        cudaFuncSetAttribute(fused_attn, cudaFuncAttributeMaxDynamicSharedMemorySize,
                             FUSED_SMEM_BYTES);
    }

    dim3 ggemm(DD / 64, MM / 128);                    // (8, 64)

    gemm512_tc<0><<<ggemm, 256>>>(Q, Wq, bq, pq);
    gemm512_tc<0><<<ggemm, 256>>>(K, Wk, bk, pk);
    gemm512_tc<0><<<ggemm, 256>>>(K, Wv, bv, pv);

    fused_attn<<<dim3(8, 64), 512, FUSED_SMEM_BYTES>>>();

    gemm512_tc<1><<<ggemm, 256>>>(po, Wo, bo, out);   // O + relu(O@Wo + bo)
    meanA_kernel<<<dim3(32, 32, 8), 256>>>(out + (size_t)MM * DD);
}